// round 1
// baseline (speedup 1.0000x reference)
#include <cuda_runtime.h>
#include <cstdint>

// Problem constants
#define B_    128
#define CIN_  64
#define NF_   16
#define COUT_ 256
#define H_    20
#define W_    20
#define HW_   400
#define K_    1024          // CIN_*NF_
#define M_    51200         // B_*HW_

#define BM    32
#define BK    64            // 4 cin x 16 nf
#define NTHREADS 256

// Tap tables: per (pixel p in [0,400), nf, tap t in [0,4)): gather index into a
// 400-element (H*W) channel plane, and bilinear weight (0 for zero-pad taps).
// Layout: [(p*NF_ + nf)*4 + t]  == p*64 + nf*4 + t
__device__ int   g_tap_idx[HW_ * NF_ * 4];
__device__ float g_tap_w  [HW_ * NF_ * 4];

__global__ void tap_kernel(const float* __restrict__ flow) {
    int t = blockIdx.x * blockDim.x + threadIdx.x;
    if (t >= NF_ * HW_) return;
    int nf = t / HW_;
    int p  = t % HW_;
    int i  = p / W_;
    int j  = p % W_;

    float fx = flow[((nf * H_ + i) * W_ + j) * 2 + 0];
    float fy = flow[((nf * H_ + i) * W_ + j) * 2 + 1];
    float ix = (float)i + fx;
    float iy = (float)j + fy;
    float bxf = floorf(ix);
    float byf = floorf(iy);
    float s  = ix - bxf;
    float tt = iy - byf;
    int bx = (int)bxf;
    int by = (int)byf;

    // NOTE: w10 intentionally equals w01 (replicates the reference's bug).
    float w00 = (1.f - s) * (1.f - tt);
    float w01 = s * (1.f - tt);
    float w10 = s * (1.f - tt);
    float w11 = s * tt;

    int   rs[4] = {bx, bx + 1, bx,     bx + 1};
    int   cs[4] = {by, by,     by + 1, by + 1};
    float ws[4] = {w00, w01, w10, w11};

    int base = p * 64 + nf * 4;
    #pragma unroll
    for (int k = 0; k < 4; k++) {
        // reference: clip to [0, 20]; index 20 hits the zero-pad row/col,
        // negatives clamp to row/col 0.
        int r = min(max(rs[k], 0), H_);
        int c = min(max(cs[k], 0), W_);
        if (r == H_ || c == W_) {
            g_tap_idx[base + k] = 0;
            g_tap_w  [base + k] = 0.f;
        } else {
            g_tap_idx[base + k] = r * W_ + c;
            g_tap_w  [base + k] = ws[k];
        }
    }
}

// Fused: generate A-tile (warped features) on the fly, multiply by combinator.
// Dynamic smem layout (floats):
//   [0,    2048)  sTapW   : [r=nf*4+t][pl]  (64 x 32)
//   [2048, 4096)  sTapIdx : [r][pl]         (as ints)
//   [4096, 6144)  sA      : [kk][pl]        (64 x 32)
//   [6144, 22528) sB      : [kk][o]         (64 x 256); reused as sOut [256][33]
__global__ __launch_bounds__(NTHREADS, 2)
void fused_kernel(const float* __restrict__ x,
                  const float* __restrict__ comb,
                  const float* __restrict__ bias,
                  float* __restrict__ out) {
    extern __shared__ float sm[];
    float* sTapW   = sm;
    int*   sTapIdx = (int*)(sm + 2048);
    float* sA      = sm + 4096;
    float* sB      = sm + 6144;
    float* sOut    = sB;

    const int tx = threadIdx.x;
    const int m0 = blockIdx.x * BM;

    // Load tap tables for this block's 32 pixels into smem.
    // e = r*32 + pl layout so later per-thread tap reads (fixed r, pl=lane)
    // are bank-conflict-free.
    for (int e = tx; e < 64 * 32; e += NTHREADS) {
        int pl = e & 31;
        int r  = e >> 5;
        int gp = (m0 + pl) % HW_;           // taps independent of batch
        sTapIdx[r * 32 + pl] = g_tap_idx[gp * 64 + r];
        sTapW  [r * 32 + pl] = g_tap_w  [gp * 64 + r];
    }

    const int pl   = tx & 31;               // pixel lane for A generation
    const int nf0  = tx >> 5;               // 0..7
    const int bpix = (m0 + pl) / HW_;
    const float* xrow = x + (size_t)bpix * CIN_ * HW_;

    const int mg = tx >> 5;                 // 0..7 (4 pixels each)
    const int ng = tx & 31;                 // 0..31 (8 strided outputs each)

    float acc[4][8];
    #pragma unroll
    for (int i = 0; i < 4; i++)
        #pragma unroll
        for (int j = 0; j < 8; j++) acc[i][j] = 0.f;

    const float* combRow = comb + (size_t)tx * K_;   // thread tx owns output row tx

    #pragma unroll 1
    for (int kc = 0; kc < K_ / BK; kc++) {
        __syncthreads();

        // Stage sB[kk][o]: thread tx reads a contiguous 256B slab of its own
        // combinator row (full sector utilization; comb is L2-resident).
        {
            const float4* src = (const float4*)(combRow + kc * BK);
            #pragma unroll
            for (int q = 0; q < BK / 4; q++) {
                float4 v = src[q];
                sB[(q * 4 + 0) * COUT_ + tx] = v.x;
                sB[(q * 4 + 1) * COUT_ + tx] = v.y;
                sB[(q * 4 + 2) * COUT_ + tx] = v.z;
                sB[(q * 4 + 3) * COUT_ + tx] = v.w;
            }
        }

        // Generate sA[kk][pl]: kk = c*16 + nf, c in [0,4) => cin = kc*4 + c.
        #pragma unroll
        for (int h = 0; h < 2; h++) {
            int nf = nf0 + 8 * h;
            int rb = nf * 4;
            int   i0 = sTapIdx[(rb + 0) * 32 + pl];
            int   i1 = sTapIdx[(rb + 1) * 32 + pl];
            int   i2 = sTapIdx[(rb + 2) * 32 + pl];
            int   i3 = sTapIdx[(rb + 3) * 32 + pl];
            float w0 = sTapW[(rb + 0) * 32 + pl];
            float w1 = sTapW[(rb + 1) * 32 + pl];
            float w2 = sTapW[(rb + 2) * 32 + pl];
            float w3 = sTapW[(rb + 3) * 32 + pl];
            #pragma unroll
            for (int c = 0; c < 4; c++) {
                const float* xr = xrow + (size_t)(kc * 4 + c) * HW_;
                float v =      xr[i0] * w0;
                v = fmaf(xr[i1], w1, v);
                v = fmaf(xr[i2], w2, v);
                v = fmaf(xr[i3], w3, v);
                sA[(c * 16 + nf) * BM + pl] = v;
            }
        }
        __syncthreads();

        // Register-blocked GEMM on the staged tiles.
        #pragma unroll 8
        for (int kk = 0; kk < BK; kk++) {
            float4 a4 = *(const float4*)(sA + kk * BM + mg * 4);  // warp broadcast
            float bv[8];
            #pragma unroll
            for (int j = 0; j < 8; j++)
                bv[j] = sB[kk * COUT_ + ng + 32 * j];             // coalesced
            #pragma unroll
            for (int j = 0; j < 8; j++) {
                acc[0][j] = fmaf(a4.x, bv[j], acc[0][j]);
                acc[1][j] = fmaf(a4.y, bv[j], acc[1][j]);
                acc[2][j] = fmaf(a4.z, bv[j], acc[2][j]);
                acc[3][j] = fmaf(a4.w, bv[j], acc[3][j]);
            }
        }
    }

    // Epilogue: stage through smem (stride 33 kills bank conflicts), then
    // coalesced global stores of out[b][o][p] (+bias).
    __syncthreads();
    #pragma unroll
    for (int j = 0; j < 8; j++) {
        int o = ng + 32 * j;
        #pragma unroll
        for (int i = 0; i < 4; i++)
            sOut[o * 33 + mg * 4 + i] = acc[i][j];
    }
    __syncthreads();

    #pragma unroll 4
    for (int r = 0; r < 32; r++) {
        int o  = (tx >> 5) + 8 * r;
        int ml = tx & 31;
        int m  = m0 + ml;
        int b  = m / HW_;
        int p  = m % HW_;
        out[((size_t)b * COUT_ + o) * HW_ + p] = sOut[o * 33 + ml] + bias[o];
    }
}

extern "C" void kernel_launch(void* const* d_in, const int* in_sizes, int n_in,
                              void* d_out, int out_size) {
    const float* x    = (const float*)d_in[0];
    const float* flow = (const float*)d_in[1];
    const float* comb = (const float*)d_in[2];
    const float* bias = (const float*)d_in[3];
    float* out = (float*)d_out;

    const int smem_bytes = 22528 * (int)sizeof(float);  // 90112
    cudaFuncSetAttribute(fused_kernel,
                         cudaFuncAttributeMaxDynamicSharedMemorySize, smem_bytes);

    tap_kernel<<<(NF_ * HW_ + 255) / 256, 256>>>(flow);
    fused_kernel<<<M_ / BM, NTHREADS, smem_bytes>>>(x, comb, bias, out);
}

// round 3
// speedup vs baseline: 3.3850x; 3.3850x over previous
#include <cuda_runtime.h>
#include <cstdint>

// ---------------- problem constants ----------------
#define B_    128
#define CIN_  64
#define NF_   16
#define COUT_ 256
#define H_    20
#define W_    20
#define HW_   400
#define K_    1024
#define M_    51200

#define MT      64       // M rows per CTA tile
#define KC      32       // K floats per chunk
#define NCHUNK  32
#define NTHREADS 256

// ---------------- smem layout (bytes) ----------------
// bias   [0,     1024)
// tapI   [1024,  17408)   64 entries x 64 rows x 4B
// tapW   [17408, 33792)
// A bufs [33792, 50176)   2 x (64 rows x 128B)
// B bufs [50176, 115712)  2 x (256 rows x 128B)
#define OFF_TAPI 1024
#define OFF_TAPW 17408
#define OFF_A    33792
#define OFF_B    50176
#define SMEM_TOTAL 115712

#define SW128(off) ((off) ^ (((off) >> 3) & 0x70))

__device__ __forceinline__ uint32_t to_tf32(float f) {
    uint32_t u;
    asm("cvt.rna.tf32.f32 %0, %1;" : "=r"(u) : "f"(f));
    return u;
}

__device__ __forceinline__ void mma_tf32(float c[4],
                                         uint32_t a0, uint32_t a1, uint32_t a2, uint32_t a3,
                                         uint32_t b0, uint32_t b1) {
    asm volatile("mma.sync.aligned.m16n8k8.row.col.f32.tf32.tf32.f32 "
                 "{%0,%1,%2,%3}, {%4,%5,%6,%7}, {%8,%9}, {%0,%1,%2,%3};"
                 : "+f"(c[0]), "+f"(c[1]), "+f"(c[2]), "+f"(c[3])
                 : "r"(a0), "r"(a1), "r"(a2), "r"(a3), "r"(b0), "r"(b1));
}

// ---------------- tap tables ([entry e = nf*4+t][pixel p]) ----------------
__device__ int   g_tap_idx[NF_ * 4 * HW_];
__device__ float g_tap_w  [NF_ * 4 * HW_];

__global__ void tap_kernel(const float* __restrict__ flow) {
    int t = blockIdx.x * blockDim.x + threadIdx.x;
    if (t >= NF_ * HW_) return;
    int nf = t / HW_;
    int p  = t % HW_;
    int i  = p / W_;
    int j  = p % W_;

    float fx = flow[((nf * H_ + i) * W_ + j) * 2 + 0];
    float fy = flow[((nf * H_ + i) * W_ + j) * 2 + 1];
    float ix = (float)i + fx;
    float iy = (float)j + fy;
    float bxf = floorf(ix), byf = floorf(iy);
    float s = ix - bxf, tt = iy - byf;
    int bx = (int)bxf, by = (int)byf;

    // NOTE: w10 intentionally equals w01 (replicates the reference's bug).
    float w00 = (1.f - s) * (1.f - tt);
    float w01 = s * (1.f - tt);
    float w10 = s * (1.f - tt);
    float w11 = s * tt;

    int   rs[4] = {bx, bx + 1, bx, bx + 1};
    int   cs[4] = {by, by, by + 1, by + 1};
    float ws[4] = {w00, w01, w10, w11};

    #pragma unroll
    for (int k = 0; k < 4; k++) {
        int r = min(max(rs[k], 0), H_);
        int c = min(max(cs[k], 0), W_);
        int e = nf * 4 + k;
        if (r == H_ || c == W_) {               // zero-pad tap
            g_tap_idx[e * HW_ + p] = 0;
            g_tap_w  [e * HW_ + p] = 0.f;
        } else {
            g_tap_idx[e * HW_ + p] = r * W_ + c;
            g_tap_w  [e * HW_ + p] = ws[k];
        }
    }
}

// ---------------- producer: stage B chunk + generate A chunk ----------------
__device__ __forceinline__ void produce(const float* __restrict__ comb,
                                        const float* __restrict__ xb,
                                        const int* __restrict__ sTapI,
                                        const float* __restrict__ sTapW,
                                        char* aBuf, char* bBuf,
                                        int kc, int tx, int ml, int nfb) {
    // ---- B: comb[o][kc*32 .. +32), 256 rows x 128B, swizzled ----
    {
        const int j  = tx & 7;                  // float4 within the 128B row
        const int ob = tx >> 3;                 // base row
        #pragma unroll
        for (int it = 0; it < 8; it++) {
            int o = ob + 32 * it;
            float4 v = *(const float4*)(comb + o * K_ + kc * KC + j * 4);
            uint32_t off = SW128((uint32_t)(o * 128 + j * 16));
            uint4 u;
            u.x = to_tf32(v.x); u.y = to_tf32(v.y);
            u.z = to_tf32(v.z); u.w = to_tf32(v.w);
            *(uint4*)(bBuf + off) = u;
        }
    }
    // ---- A: 64 rows x 32 k (2 cin x 16 nf); this thread: row ml, nf nfb..nfb+3 ----
    {
        const float* xr0 = xb + (size_t)(kc * 2) * HW_;
        const float* xr1 = xr0 + HW_;
        uint4 u0, u1;
        uint32_t* p0 = (uint32_t*)&u0;
        uint32_t* p1 = (uint32_t*)&u1;
        #pragma unroll
        for (int q = 0; q < 4; q++) {
            const int rb = (nfb + q) * 4;
            int   i0 = sTapI[(rb + 0) * MT + ml];
            int   i1 = sTapI[(rb + 1) * MT + ml];
            int   i2 = sTapI[(rb + 2) * MT + ml];
            int   i3 = sTapI[(rb + 3) * MT + ml];
            float w0 = sTapW[(rb + 0) * MT + ml];
            float w1 = sTapW[(rb + 1) * MT + ml];
            float w2 = sTapW[(rb + 2) * MT + ml];
            float w3 = sTapW[(rb + 3) * MT + ml];
            float a0 = xr0[i0] * w0;
            a0 = fmaf(xr0[i1], w1, a0);
            a0 = fmaf(xr0[i2], w2, a0);
            a0 = fmaf(xr0[i3], w3, a0);
            p0[q] = to_tf32(a0);
            float a1 = xr1[i0] * w0;
            a1 = fmaf(xr1[i1], w1, a1);
            a1 = fmaf(xr1[i2], w2, a1);
            a1 = fmaf(xr1[i3], w3, a1);
            p1[q] = to_tf32(a1);
        }
        // kk = cl*16 + nf
        uint32_t o0 = SW128((uint32_t)(ml * 128 + nfb * 4));        // cl=0
        uint32_t o1 = SW128((uint32_t)(ml * 128 + 64 + nfb * 4));   // cl=1
        *(uint4*)(aBuf + o0) = u0;
        *(uint4*)(aBuf + o1) = u1;
    }
}

// ---------------- consumer: 4 x (k=8) mma steps on one chunk ----------------
__device__ __forceinline__ void consume(const char* aBuf, const char* bBuf,
                                        float acc[2][8][4],
                                        int r, int c, int warpM, int warpN) {
    #pragma unroll
    for (int s = 0; s < 4; s++) {
        const uint32_t kO  = (uint32_t)(s * 32 + c * 4);
        const uint32_t swb = (uint32_t)(r << 4);
        uint32_t b0[8], b1[8];
        #pragma unroll
        for (int j = 0; j < 8; j++) {
            uint32_t base = (uint32_t)((warpN * 64 + j * 8 + r) * 128);
            b0[j] = *(const uint32_t*)(bBuf + base + (kO ^ swb));
            b1[j] = *(const uint32_t*)(bBuf + base + ((kO + 16) ^ swb));
        }
        #pragma unroll
        for (int wm = 0; wm < 2; wm++) {
            uint32_t mRow = (uint32_t)(warpM * 32 + wm * 16 + r);
            uint32_t sw   = (mRow & 7) << 4;
            uint32_t ro   = mRow * 128;
            uint32_t a0 = *(const uint32_t*)(aBuf + ro + (kO ^ sw));
            uint32_t a1 = *(const uint32_t*)(aBuf + ro + 1024 + (kO ^ sw));
            uint32_t a2 = *(const uint32_t*)(aBuf + ro + ((kO + 16) ^ sw));
            uint32_t a3 = *(const uint32_t*)(aBuf + ro + 1024 + ((kO + 16) ^ sw));
            #pragma unroll
            for (int j = 0; j < 8; j++)
                mma_tf32(acc[wm][j], a0, a1, a2, a3, b0[j], b1[j]);
        }
    }
}

// ---------------- fused kernel ----------------
__global__ __launch_bounds__(NTHREADS, 2)
void mma_kernel(const float* __restrict__ x,
                const float* __restrict__ comb,
                const float* __restrict__ bias,
                float* __restrict__ out) {
    extern __shared__ char smem[];
    float* sBias = (float*)smem;
    int*   sTapI = (int*)(smem + OFF_TAPI);
    float* sTapW = (float*)(smem + OFF_TAPW);

    const int tx = threadIdx.x;
    const int m0 = blockIdx.x * MT;

    sBias[tx] = bias[tx];
    for (int i = tx; i < 64 * MT; i += NTHREADS) {
        int e  = i >> 6;
        int ml = i & 63;
        int p  = (m0 + ml) % HW_;
        sTapI[e * MT + ml] = g_tap_idx[e * HW_ + p];
        sTapW[e * MT + ml] = g_tap_w  [e * HW_ + p];
    }
    __syncthreads();

    const int ml  = tx & 63;
    const int nfb = (tx >> 6) * 4;
    const float* xb = x + (size_t)((m0 + ml) / HW_) * CIN_ * HW_;

    const int lane  = tx & 31;
    const int r     = lane >> 2;
    const int c     = lane & 3;
    const int wid   = tx >> 5;
    const int warpM = wid & 1;
    const int warpN = wid >> 1;

    float acc[2][8][4];
    #pragma unroll
    for (int i = 0; i < 2; i++)
        #pragma unroll
        for (int j = 0; j < 8; j++)
            #pragma unroll
            for (int q = 0; q < 4; q++) acc[i][j][q] = 0.f;

    produce(comb, xb, sTapI, sTapW, smem + OFF_A, smem + OFF_B, 0, tx, ml, nfb);
    __syncthreads();

    #pragma unroll 1
    for (int kc = 0; kc < NCHUNK; kc++) {
        char* aC = smem + OFF_A + (kc & 1) * 8192;
        char* bC = smem + OFF_B + (kc & 1) * 32768;
        if (kc + 1 < NCHUNK)
            produce(comb, xb, sTapI, sTapW,
                    smem + OFF_A + ((kc + 1) & 1) * 8192,
                    smem + OFF_B + ((kc + 1) & 1) * 32768,
                    kc + 1, tx, ml, nfb);
        consume(aC, bC, acc, r, c, warpM, warpN);
        __syncthreads();
    }

    // ---- epilogue: direct from accumulators, 32B-coalesced over m ----
    #pragma unroll
    for (int wm = 0; wm < 2; wm++) {
        int mr0 = m0 + warpM * 32 + wm * 16 + r;
        int mr1 = mr0 + 8;
        int b0i = mr0 / HW_, p0 = mr0 - b0i * HW_;
        int b1i = mr1 / HW_, p1 = mr1 - b1i * HW_;
        float* o0 = out + (size_t)b0i * COUT_ * HW_ + p0;
        float* o1 = out + (size_t)b1i * COUT_ * HW_ + p1;
        #pragma unroll
        for (int j = 0; j < 8; j++) {
            int n0 = warpN * 64 + j * 8 + 2 * c;
            float bz0 = sBias[n0], bz1 = sBias[n0 + 1];
            o0[(size_t)n0 * HW_]       = acc[wm][j][0] + bz0;
            o0[(size_t)(n0 + 1) * HW_] = acc[wm][j][1] + bz1;
            o1[(size_t)n0 * HW_]       = acc[wm][j][2] + bz0;
            o1[(size_t)(n0 + 1) * HW_] = acc[wm][j][3] + bz1;
        }
    }
}

extern "C" void kernel_launch(void* const* d_in, const int* in_sizes, int n_in,
                              void* d_out, int out_size) {
    const float* x    = (const float*)d_in[0];
    const float* flow = (const float*)d_in[1];
    const float* comb = (const float*)d_in[2];
    const float* bias = (const float*)d_in[3];
    float* out = (float*)d_out;

    cudaFuncSetAttribute(mma_kernel,
                         cudaFuncAttributeMaxDynamicSharedMemorySize, SMEM_TOTAL);

    tap_kernel<<<(NF_ * HW_ + 255) / 256, 256>>>(flow);
    mma_kernel<<<M_ / MT, NTHREADS, SMEM_TOTAL>>>(x, comb, bias, out);
}

// round 4
// speedup vs baseline: 3.4767x; 1.0271x over previous
#include <cuda_runtime.h>
#include <cstdint>

// ---------------- problem constants ----------------
#define B_    128
#define CIN_  64
#define NF_   16
#define COUT_ 256
#define H_    20
#define W_    20
#define HW_   400
#define K_    1024
#define M_    51200

#define MT      128      // M rows per CTA tile
#define KC      32       // K floats per chunk
#define NCHUNK  32
#define NTHREADS 256

// ---------------- smem layout (bytes) ----------------
// bias [0, 1024)
// A    [1024,  33792)   2 x (128 rows x 128B)
// B    [33792, 99328)   2 x (256 rows x 128B)
#define OFF_A    1024
#define OFF_B    33792
#define SMEM_TOTAL 99328

__device__ __forceinline__ uint32_t to_tf32(float f) {
    uint32_t u;
    asm("cvt.rna.tf32.f32 %0, %1;" : "=r"(u) : "f"(f));
    return u;
}

__device__ __forceinline__ void mma_tf32(float c[4],
                                         uint32_t a0, uint32_t a1, uint32_t a2, uint32_t a3,
                                         uint32_t b0, uint32_t b1) {
    asm volatile("mma.sync.aligned.m16n8k8.row.col.f32.tf32.tf32.f32 "
                 "{%0,%1,%2,%3}, {%4,%5,%6,%7}, {%8,%9}, {%0,%1,%2,%3};"
                 : "+f"(c[0]), "+f"(c[1]), "+f"(c[2]), "+f"(c[3])
                 : "r"(a0), "r"(a1), "r"(a2), "r"(a3), "r"(b0), "r"(b1));
}

// ---------------- device scratch ----------------
// Pre-swizzled tf32 comb images: per chunk kc, the exact 32KB smem B-buffer
// image (rows o x 128B, 16B groups permuted q^=(o&7)).
__device__ uint4    g_combT[NCHUNK * 2048];           // 1 MB
__device__ uint16_t g_tap_off[NF_ * 4 * HW_];         // byte offsets into a plane
__device__ float    g_tap_w  [NF_ * 4 * HW_];

// ---------------- prologue: tap tables ----------------
__global__ void tap_kernel(const float* __restrict__ flow) {
    int t = blockIdx.x * blockDim.x + threadIdx.x;
    if (t >= NF_ * HW_) return;
    int nf = t / HW_;
    int p  = t % HW_;
    int i  = p / W_;
    int j  = p % W_;

    float fx = flow[((nf * H_ + i) * W_ + j) * 2 + 0];
    float fy = flow[((nf * H_ + i) * W_ + j) * 2 + 1];
    float ix = (float)i + fx;
    float iy = (float)j + fy;
    float bxf = floorf(ix), byf = floorf(iy);
    float s = ix - bxf, tt = iy - byf;
    int bx = (int)bxf, by = (int)byf;

    // NOTE: w10 intentionally equals w01 (replicates the reference's bug).
    float w00 = (1.f - s) * (1.f - tt);
    float w01 = s * (1.f - tt);
    float w10 = s * (1.f - tt);
    float w11 = s * tt;

    int   rs[4] = {bx, bx + 1, bx, bx + 1};
    int   cs[4] = {by, by, by + 1, by + 1};
    float ws[4] = {w00, w01, w10, w11};

    #pragma unroll
    for (int k = 0; k < 4; k++) {
        int r = min(max(rs[k], 0), H_);
        int c = min(max(cs[k], 0), W_);
        int e = nf * 4 + k;
        if (r == H_ || c == W_) {                 // zero-pad tap
            g_tap_off[e * HW_ + p] = 0;
            g_tap_w  [e * HW_ + p] = 0.f;
        } else {
            g_tap_off[e * HW_ + p] = (uint16_t)((r * W_ + c) * 4);
            g_tap_w  [e * HW_ + p] = ws[k];
        }
    }
}

// ---------------- prologue: comb -> tf32, pre-swizzled chunk images ----------
__global__ void comb_prep(const float* __restrict__ comb) {
    int t = blockIdx.x * blockDim.x + threadIdx.x;   // 32 * 256 threads
    if (t >= NCHUNK * COUT_) return;
    int kc = t >> 8;
    int o  = t & 255;
    #pragma unroll
    for (int q = 0; q < 8; q++) {
        float4 v = *(const float4*)(comb + o * K_ + kc * KC + q * 4);
        uint4 u;
        u.x = to_tf32(v.x); u.y = to_tf32(v.y);
        u.z = to_tf32(v.z); u.w = to_tf32(v.w);
        g_combT[kc * 2048 + o * 8 + (q ^ (o & 7))] = u;
    }
}

// ---------------- fused kernel ----------------
__global__ __launch_bounds__(NTHREADS, 1)
void mma_kernel(const float* __restrict__ x,
                const float* __restrict__ bias,
                float* __restrict__ out) {
    extern __shared__ char smem[];
    float* sBias = (float*)smem;

    const int tx = threadIdx.x;
    const int m0 = blockIdx.x * MT;

    sBias[tx] = bias[tx];

    // ---- hoist taps into registers (kc-invariant) ----
    const int ml = tx & 127;
    const int hh = tx >> 7;                  // nf half: owns nf = hh*8 + q, q<8
    const int m  = m0 + ml;
    const int p  = m % HW_;
    const char* xb = (const char*)(x + (size_t)(m / HW_) * CIN_ * HW_);

    uint32_t tapPk[8][2];
    float    tapW [8][4];
    #pragma unroll
    for (int q = 0; q < 8; q++) {
        int e = (hh * 8 + q) * 4;
        uint32_t t0 = g_tap_off[(e + 0) * HW_ + p];
        uint32_t t1 = g_tap_off[(e + 1) * HW_ + p];
        uint32_t t2 = g_tap_off[(e + 2) * HW_ + p];
        uint32_t t3 = g_tap_off[(e + 3) * HW_ + p];
        tapPk[q][0] = t0 | (t1 << 16);
        tapPk[q][1] = t2 | (t3 << 16);
        tapW[q][0] = g_tap_w[(e + 0) * HW_ + p];
        tapW[q][1] = g_tap_w[(e + 1) * HW_ + p];
        tapW[q][2] = g_tap_w[(e + 2) * HW_ + p];
        tapW[q][3] = g_tap_w[(e + 3) * HW_ + p];
    }

    const int lane  = tx & 31;
    const int r     = lane >> 2;
    const int c     = lane & 3;
    const int wid   = tx >> 5;
    const int warpM = wid & 1;               // 2 M-groups of 64
    const int warpN = wid >> 1;              // 4 N-groups of 64

    float acc[4][8][4];
    #pragma unroll
    for (int i = 0; i < 4; i++)
        #pragma unroll
        for (int j = 0; j < 8; j++)
            #pragma unroll
            for (int q = 0; q < 4; q++) acc[i][j][q] = 0.f;

    const uint32_t swx = (uint32_t)((ml & 7) << 4);

    // ---- producer lambda-ish (macro-free inline) ----
    auto produce = [&](int kc) {
        // B: straight copy of pre-swizzled image (coalesced both sides)
        {
            const uint4* src = g_combT + kc * 2048;
            uint4* dst = (uint4*)(smem + OFF_B + (kc & 1) * 32768);
            #pragma unroll
            for (int i = 0; i < 8; i++)
                dst[i * 256 + tx] = __ldg(src + i * 256 + tx);
        }
        // A: gather-generate 16 elements (8 nf x 2 cin), swizzled STS.128
        {
            const char* x0 = xb + (size_t)(kc * 2) * HW_ * 4;
            const char* x1 = x0 + HW_ * 4;
            float va[8], vb[8];
            #pragma unroll
            for (int q = 0; q < 8; q++) {
                uint32_t pk0 = tapPk[q][0], pk1 = tapPk[q][1];
                uint32_t i0 = pk0 & 0xFFFFu, i1 = pk0 >> 16;
                uint32_t i2 = pk1 & 0xFFFFu, i3 = pk1 >> 16;
                float w0 = tapW[q][0], w1 = tapW[q][1];
                float w2 = tapW[q][2], w3 = tapW[q][3];
                float a0 = *(const float*)(x0 + i0) * w0;
                a0 = fmaf(*(const float*)(x0 + i1), w1, a0);
                a0 = fmaf(*(const float*)(x0 + i2), w2, a0);
                a0 = fmaf(*(const float*)(x0 + i3), w3, a0);
                va[q] = a0;
                float a1 = *(const float*)(x1 + i0) * w0;
                a1 = fmaf(*(const float*)(x1 + i1), w1, a1);
                a1 = fmaf(*(const float*)(x1 + i2), w2, a1);
                a1 = fmaf(*(const float*)(x1 + i3), w3, a1);
                vb[q] = a1;
            }
            char* aBuf = smem + OFF_A + (kc & 1) * 16384;
            char* rowb = aBuf + ml * 128;
            // word k = cl*16 + hh*8 + q ; byte groups: cl*64 + hh*32 + g*16
            uint4 u;
            u.x = to_tf32(va[0]); u.y = to_tf32(va[1]);
            u.z = to_tf32(va[2]); u.w = to_tf32(va[3]);
            *(uint4*)(rowb + (((uint32_t)(hh * 32 +  0)) ^ swx)) = u;
            u.x = to_tf32(va[4]); u.y = to_tf32(va[5]);
            u.z = to_tf32(va[6]); u.w = to_tf32(va[7]);
            *(uint4*)(rowb + (((uint32_t)(hh * 32 + 16)) ^ swx)) = u;
            u.x = to_tf32(vb[0]); u.y = to_tf32(vb[1]);
            u.z = to_tf32(vb[2]); u.w = to_tf32(vb[3]);
            *(uint4*)(rowb + (((uint32_t)(64 + hh * 32 +  0)) ^ swx)) = u;
            u.x = to_tf32(vb[4]); u.y = to_tf32(vb[5]);
            u.z = to_tf32(vb[6]); u.w = to_tf32(vb[7]);
            *(uint4*)(rowb + (((uint32_t)(64 + hh * 32 + 16)) ^ swx)) = u;
        }
    };

    produce(0);
    __syncthreads();

    #pragma unroll 1
    for (int kc = 0; kc < NCHUNK; kc++) {
        const char* aC = smem + OFF_A + (kc & 1) * 16384;
        const char* bC = smem + OFF_B + (kc & 1) * 32768;
        if (kc + 1 < NCHUNK) produce(kc + 1);

        #pragma unroll
        for (int s = 0; s < 4; s++) {
            const uint32_t kO = (uint32_t)(s * 32 + c * 4);
            uint32_t b0[8], b1[8];
            #pragma unroll
            for (int j = 0; j < 8; j++) {
                uint32_t n   = (uint32_t)(warpN * 64 + j * 8 + r);
                uint32_t swn = (n & 7) << 4;
                const char* rb = bC + n * 128;
                b0[j] = *(const uint32_t*)(rb + (kO ^ swn));
                b1[j] = *(const uint32_t*)(rb + ((kO + 16) ^ swn));
            }
            #pragma unroll
            for (int wm = 0; wm < 4; wm++) {
                uint32_t row = (uint32_t)(warpM * 64 + wm * 16 + r);
                uint32_t swa = (row & 7) << 4;
                const char* ra = aC + row * 128;
                uint32_t a0 = *(const uint32_t*)(ra + (kO ^ swa));
                uint32_t a1 = *(const uint32_t*)(ra + 1024 + (kO ^ swa));
                uint32_t a2 = *(const uint32_t*)(ra + ((kO + 16) ^ swa));
                uint32_t a3 = *(const uint32_t*)(ra + 1024 + ((kO + 16) ^ swa));
                #pragma unroll
                for (int j = 0; j < 8; j++)
                    mma_tf32(acc[wm][j], a0, a1, a2, a3, b0[j], b1[j]);
            }
        }
        __syncthreads();
    }

    // ---- epilogue ----
    #pragma unroll
    for (int wm = 0; wm < 4; wm++) {
        int mr0 = m0 + warpM * 64 + wm * 16 + r;
        int mr1 = mr0 + 8;
        int b0i = mr0 / HW_, p0 = mr0 - b0i * HW_;
        int b1i = mr1 / HW_, p1 = mr1 - b1i * HW_;
        float* o0 = out + (size_t)b0i * COUT_ * HW_ + p0;
        float* o1 = out + (size_t)b1i * COUT_ * HW_ + p1;
        #pragma unroll
        for (int j = 0; j < 8; j++) {
            int n0 = warpN * 64 + j * 8 + 2 * c;
            float bz0 = sBias[n0], bz1 = sBias[n0 + 1];
            o0[(size_t)n0 * HW_]       = acc[wm][j][0] + bz0;
            o0[(size_t)(n0 + 1) * HW_] = acc[wm][j][1] + bz1;
            o1[(size_t)n0 * HW_]       = acc[wm][j][2] + bz0;
            o1[(size_t)(n0 + 1) * HW_] = acc[wm][j][3] + bz1;
        }
    }
}

extern "C" void kernel_launch(void* const* d_in, const int* in_sizes, int n_in,
                              void* d_out, int out_size) {
    const float* x    = (const float*)d_in[0];
    const float* flow = (const float*)d_in[1];
    const float* comb = (const float*)d_in[2];
    const float* bias = (const float*)d_in[3];
    float* out = (float*)d_out;

    cudaFuncSetAttribute(mma_kernel,
                         cudaFuncAttributeMaxDynamicSharedMemorySize, SMEM_TOTAL);

    tap_kernel<<<(NF_ * HW_ + 255) / 256, 256>>>(flow);
    comb_prep<<<(NCHUNK * COUT_ + 255) / 256, 256>>>(comb);
    mma_kernel<<<M_ / MT, NTHREADS, SMEM_TOTAL>>>(x, bias, out);
}

// round 5
// speedup vs baseline: 5.4528x; 1.5684x over previous
#include <cuda_runtime.h>
#include <cstdint>

// ---------------- problem constants ----------------
#define B_    128
#define CIN_  64
#define NF_   16
#define COUT_ 256
#define H_    20
#define W_    20
#define HW_   400
#define K_    1024
#define M_    51200

#define MT      128      // M rows per CTA tile
#define KC      64       // K per chunk = 4 cin x 16 nf
#define NCHUNK  16
#define NTHREADS 256

// ---------------- smem layout (bytes) ----------------
// bias [0, 1024)
// A    [1024,  33792)   2 x (128 rows x 128B)  fp16
// B    [33792, 99328)   2 x (256 rows x 128B)  fp16
#define OFF_A    1024
#define OFF_B    33792
#define SMEM_TOTAL 99328

// ---------------- device scratch ----------------
__device__ float2   g_xpair[B_ * CIN_ * HW_];        // 26.2MB: (x[p], x[p+1])
__device__ uint4    g_combB[NCHUNK * COUT_ * 8];     // 512KB pre-swizzled fp16 images
__device__ uint32_t g_tapO[NF_ * HW_];               // packed byte offsets (2x u16)
__device__ float4   g_tapW[NF_ * HW_];               // remapped pair weights

// ---------------- small helpers ----------------
__device__ __forceinline__ uint32_t smem_u32(const void* p) {
    uint32_t a;
    asm("{ .reg .u64 t; cvta.to.shared.u64 t, %1; cvt.u32.u64 %0, t; }" : "=r"(a) : "l"(p));
    return a;
}
__device__ __forceinline__ uint32_t pack_h2(float lo, float hi) {
    uint32_t u;
    asm("cvt.rn.f16x2.f32 %0, %1, %2;" : "=r"(u) : "f"(hi), "f"(lo));  // {hi, lo}
    return u;
}
__device__ __forceinline__ void ldsm_x4(uint32_t& r0, uint32_t& r1, uint32_t& r2, uint32_t& r3,
                                        uint32_t addr) {
    asm volatile("ldmatrix.sync.aligned.m8n8.x4.shared.b16 {%0,%1,%2,%3}, [%4];"
                 : "=r"(r0), "=r"(r1), "=r"(r2), "=r"(r3) : "r"(addr));
}
__device__ __forceinline__ void mma_f16(float c[4], uint32_t a0, uint32_t a1, uint32_t a2,
                                        uint32_t a3, uint32_t b0, uint32_t b1) {
    asm volatile("mma.sync.aligned.m16n8k16.row.col.f32.f16.f16.f32 "
                 "{%0,%1,%2,%3}, {%4,%5,%6,%7}, {%8,%9}, {%0,%1,%2,%3};"
                 : "+f"(c[0]), "+f"(c[1]), "+f"(c[2]), "+f"(c[3])
                 : "r"(a0), "r"(a1), "r"(a2), "r"(a3), "r"(b0), "r"(b1));
}
__device__ __forceinline__ void cp16(uint32_t dst, const void* src) {
    asm volatile("cp.async.cg.shared.global [%0], [%1], 16;" :: "r"(dst), "l"(src) : "memory");
}

// ---------------- prologue: x -> overlapping pairs ----------------
__global__ void xpair_kernel(const float* __restrict__ x) {
    int t = blockIdx.x * blockDim.x + threadIdx.x;
    if (t >= B_ * CIN_ * HW_) return;
    int p = t % HW_;
    float v0 = x[t];
    float v1 = (p < HW_ - 1) ? x[t + 1] : 0.f;
    g_xpair[t] = make_float2(v0, v1);
}

// ---------------- prologue: tap tables (paired form) ----------------
__global__ void tap_kernel(const float* __restrict__ flow) {
    int t = blockIdx.x * blockDim.x + threadIdx.x;
    if (t >= NF_ * HW_) return;
    int nf = t / HW_;
    int p  = t % HW_;
    int i  = p / W_;
    int j  = p % W_;

    float fx = flow[((nf * H_ + i) * W_ + j) * 2 + 0];
    float fy = flow[((nf * H_ + i) * W_ + j) * 2 + 1];
    float ix = (float)i + fx;
    float iy = (float)j + fy;
    float bxf = floorf(ix), byf = floorf(iy);
    float s = ix - bxf, tt = iy - byf;
    int bx = (int)bxf, by = (int)byf;

    // NOTE: w10 intentionally equals w01 (replicates the reference's bug).
    float w00 = (1.f - s) * (1.f - tt);   // (bx,   by)
    float w01 = s * (1.f - tt);           // (bx+1, by)
    float w10 = s * (1.f - tt);           // (bx,   by+1)
    float w11 = s * tt;                   // (bx+1, by+1)

    // columns: tap-col "by" carries (w00 row bx, w01 row bx+1);
    //          tap-col "by+1" carries (w10, w11)
    int cc0 = min(max(by, 0), W_);     bool cv0 = cc0 < W_;
    int cc1 = min(max(by + 1, 0), W_); bool cv1 = cc1 < W_;
    int cb  = min(max(by, 0), W_ - 2);
    float m0lo = (cv0 && cc0 == cb)     ? 1.f : 0.f;
    float m0hi = (cv0 && cc0 == cb + 1) ? 1.f : 0.f;
    float m1lo = (cv1 && cc1 == cb)     ? 1.f : 0.f;
    float m1hi = (cv1 && cc1 == cb + 1) ? 1.f : 0.f;

    int rr0 = min(max(bx, 0), H_);     bool rv0 = rr0 < H_;
    int rr1 = min(max(bx + 1, 0), H_); bool rv1 = rr1 < H_;
    int r0c = rv0 ? rr0 : 0;
    int r1c = rv1 ? rr1 : 0;

    float u0 = rv0 ? (w00 * m0lo + w10 * m1lo) : 0.f;
    float u1 = rv0 ? (w00 * m0hi + w10 * m1hi) : 0.f;
    float v0 = rv1 ? (w01 * m0lo + w11 * m1lo) : 0.f;
    float v1 = rv1 ? (w01 * m0hi + w11 * m1hi) : 0.f;

    uint32_t o0 = (uint32_t)((r0c * W_ + cb) * 8);   // byte offset into float2 plane
    uint32_t o1 = (uint32_t)((r1c * W_ + cb) * 8);
    g_tapO[nf * HW_ + p] = o0 | (o1 << 16);
    g_tapW[nf * HW_ + p] = make_float4(u0, u1, v0, v1);
}

// ---------------- prologue: comb -> fp16, pre-swizzled chunk images ----------
__global__ void comb_prep(const float* __restrict__ comb) {
    int t = blockIdx.x * blockDim.x + threadIdx.x;
    if (t >= NCHUNK * COUT_) return;
    int kc = t >> 8;
    int o  = t & 255;
    const float* src = comb + o * K_ + kc * KC;
    #pragma unroll
    for (int g = 0; g < 8; g++) {
        float4 a = *(const float4*)(src + g * 8);
        float4 b = *(const float4*)(src + g * 8 + 4);
        uint4 u;
        u.x = pack_h2(a.x, a.y); u.y = pack_h2(a.z, a.w);
        u.z = pack_h2(b.x, b.y); u.w = pack_h2(b.z, b.w);
        g_combB[(kc * COUT_ + o) * 8 + (g ^ (o & 7))] = u;
    }
}

// ---------------- fused kernel ----------------
__global__ __launch_bounds__(NTHREADS, 1)
void mma_kernel(const float* __restrict__ bias, float* __restrict__ out) {
    extern __shared__ char smem[];
    float* sBias = (float*)smem;
    const uint32_t sbase = smem_u32(smem);

    const int tx = threadIdx.x;
    const int m0 = blockIdx.x * MT;

    sBias[tx] = bias[tx];

    // ---- hoist taps: thread owns row ml, nf half hh (8 nf) ----
    const int ml = tx & 127;
    const int hh = tx >> 7;
    const int m  = m0 + ml;
    const int p  = m % HW_;
    const char* xpb = (const char*)(g_xpair + (size_t)(m / HW_) * CIN_ * HW_);

    uint32_t tapO[8];
    float4   tapW[8];
    #pragma unroll
    for (int q = 0; q < 8; q++) {
        int nf = hh * 8 + q;
        tapO[q] = g_tapO[nf * HW_ + p];
        tapW[q] = g_tapW[nf * HW_ + p];
    }

    const int lane  = tx & 31;
    const int wid   = tx >> 5;
    const int warpM = wid & 1;               // 2 M-groups of 64
    const int warpN = wid >> 1;              // 4 N-groups of 64
    const uint32_t swx = (uint32_t)((ml & 7) << 4);

    float acc[4][8][4];
    #pragma unroll
    for (int i = 0; i < 4; i++)
        #pragma unroll
        for (int j = 0; j < 8; j++)
            #pragma unroll
            for (int q = 0; q < 4; q++) acc[i][j][q] = 0.f;

    auto produce = [&](int kc) {
        // B: async copy of pre-swizzled fp16 image (32KB)
        {
            const char* src = (const char*)(g_combB + (size_t)kc * COUT_ * 8);
            uint32_t dst = sbase + OFF_B + (kc & 1) * 32768;
            #pragma unroll
            for (int i = 0; i < 8; i++)
                cp16(dst + (i * 256 + tx) * 16, src + (i * 256 + tx) * 16);
            asm volatile("cp.async.commit_group;" ::: "memory");
        }
        // A: paired gathers, 8 nf x 4 cin
        {
            const char* xc = xpb + (size_t)(kc * 4) * (HW_ * 8);
            float val[4][8];
            #pragma unroll
            for (int q = 0; q < 8; q++) {
                uint32_t pk = tapO[q];
                uint32_t o0 = pk & 0xFFFFu, o1 = pk >> 16;
                float4 w = tapW[q];
                #pragma unroll
                for (int cl = 0; cl < 4; cl++) {
                    const char* pl = xc + cl * (HW_ * 8);
                    float2 lo = *(const float2*)(pl + o0);
                    float2 hi = *(const float2*)(pl + o1);
                    float v = lo.x * w.x;
                    v = fmaf(lo.y, w.y, v);
                    v = fmaf(hi.x, w.z, v);
                    v = fmaf(hi.y, w.w, v);
                    val[cl][q] = v;
                }
            }
            uint32_t abase = sbase + OFF_A + (kc & 1) * 16384 + ml * 128;
            #pragma unroll
            for (int cl = 0; cl < 4; cl++) {
                uint4 u;
                u.x = pack_h2(val[cl][0], val[cl][1]);
                u.y = pack_h2(val[cl][2], val[cl][3]);
                u.z = pack_h2(val[cl][4], val[cl][5]);
                u.w = pack_h2(val[cl][6], val[cl][7]);
                uint32_t addr = abase + (((uint32_t)(cl * 32 + 16 * hh)) ^ swx);
                asm volatile("st.shared.v4.b32 [%0], {%1,%2,%3,%4};"
                             :: "r"(addr), "r"(u.x), "r"(u.y), "r"(u.z), "r"(u.w) : "memory");
            }
        }
    };

    // ldmatrix address: 8x8 tiles at (rowBase, kByte), canonical x4 lane map
    auto lm_addr = [&](uint32_t base, int rowBase, int kByte) -> uint32_t {
        int r  = rowBase + (lane & 7) + 8 * ((lane >> 3) & 1);
        int cb = kByte + 16 * (lane >> 4);
        return base + r * 128 + (uint32_t)(cb ^ ((r & 7) << 4));
    };

    produce(0);
    asm volatile("cp.async.wait_group 0;" ::: "memory");
    __syncthreads();

    #pragma unroll 1
    for (int kc = 0; kc < NCHUNK; kc++) {
        if (kc + 1 < NCHUNK) produce(kc + 1);

        const uint32_t aBuf = sbase + OFF_A + (kc & 1) * 16384;
        const uint32_t bBuf = sbase + OFF_B + (kc & 1) * 32768;

        #pragma unroll
        for (int s = 0; s < 4; s++) {
            const int kB = s * 32;
            uint32_t bb[4][4];
            #pragma unroll
            for (int jn = 0; jn < 4; jn++)
                ldsm_x4(bb[jn][0], bb[jn][1], bb[jn][2], bb[jn][3],
                        lm_addr(bBuf, warpN * 64 + jn * 16, kB));
            #pragma unroll
            for (int wm = 0; wm < 4; wm++) {
                uint32_t a0, a1, a2, a3;
                ldsm_x4(a0, a1, a2, a3, lm_addr(aBuf, warpM * 64 + wm * 16, kB));
                #pragma unroll
                for (int jn = 0; jn < 4; jn++) {
                    mma_f16(acc[wm][jn * 2 + 0], a0, a1, a2, a3, bb[jn][0], bb[jn][2]);
                    mma_f16(acc[wm][jn * 2 + 1], a0, a1, a2, a3, bb[jn][1], bb[jn][3]);
                }
            }
        }
        asm volatile("cp.async.wait_group 0;" ::: "memory");
        __syncthreads();
    }

    // ---- epilogue ----
    const int r = lane >> 2;
    const int c = lane & 3;
    #pragma unroll
    for (int wm = 0; wm < 4; wm++) {
        int mr0 = m0 + warpM * 64 + wm * 16 + r;
        int mr1 = mr0 + 8;
        int b0i = mr0 / HW_, p0 = mr0 - b0i * HW_;
        int b1i = mr1 / HW_, p1 = mr1 - b1i * HW_;
        float* o0 = out + (size_t)b0i * COUT_ * HW_ + p0;
        float* o1 = out + (size_t)b1i * COUT_ * HW_ + p1;
        #pragma unroll
        for (int j = 0; j < 8; j++) {
            int n0 = warpN * 64 + (j >> 1) * 16 + (j & 1) * 8 + 2 * c;
            float bz0 = sBias[n0], bz1 = sBias[n0 + 1];
            o0[(size_t)n0 * HW_]       = acc[wm][j][0] + bz0;
            o0[(size_t)(n0 + 1) * HW_] = acc[wm][j][1] + bz1;
            o1[(size_t)n0 * HW_]       = acc[wm][j][2] + bz0;
            o1[(size_t)(n0 + 1) * HW_] = acc[wm][j][3] + bz1;
        }
    }
}

extern "C" void kernel_launch(void* const* d_in, const int* in_sizes, int n_in,
                              void* d_out, int out_size) {
    const float* x    = (const float*)d_in[0];
    const float* flow = (const float*)d_in[1];
    const float* comb = (const float*)d_in[2];
    const float* bias = (const float*)d_in[3];
    float* out = (float*)d_out;

    cudaFuncSetAttribute(mma_kernel,
                         cudaFuncAttributeMaxDynamicSharedMemorySize, SMEM_TOTAL);

    xpair_kernel<<<(B_ * CIN_ * HW_ + 255) / 256, 256>>>(x);
    tap_kernel<<<(NF_ * HW_ + 255) / 256, 256>>>(flow);
    comb_prep<<<(NCHUNK * COUT_ + 255) / 256, 256>>>(comb);
    mma_kernel<<<M_ / MT, NTHREADS, SMEM_TOTAL>>>(bias, out);
}